// round 11
// baseline (speedup 1.0000x reference)
#include <cuda_runtime.h>
#include <stdint.h>
#include <math.h>

#define NEGV  -1e30f
#define SWT   128         // threads per sw CTA (2 CTAs per batch via cluster)
#define FU    512         // feed u-rows
#define LOG2E 1.4426950408889634f
#define LN2   0.6931471805599453f

// ---- static device scratch ----
__device__ float  g_S[4 * 512 * 512];          // plain score matrices
__device__ float  g_n2[2 * 4 * 512];           // row norms
__device__ float4 g_Sf4[4 * FU * 256];         // skewed S feed (base-2 scaled)
__device__ float4 g_gof4[FU * 256];            // skewed go feed (scaled)
__device__ float4 g_gef4[FU * 256];            // skewed ge feed (scaled)
__device__ float4 g_Df4[4 * FU * 256];         // skewed D output (base-2 domain)
__device__ float  g_pm[256], g_ps[256];        // LSE partials (64 per batch)

__device__ __forceinline__ float ex2a(float x) {
    float r; asm("ex2.approx.ftz.f32 %0, %1;" : "=f"(r) : "f"(x)); return r;
}
__device__ __forceinline__ float lg2a(float x) {
    float r; asm("lg2.approx.ftz.f32 %0, %1;" : "=f"(r) : "f"(x)); return r;
}
__device__ __forceinline__ float lse2b(float a, float b) {
    float m = fmaxf(a, b), n = fminf(a, b);
    return m + lg2a(1.0f + ex2a(n - m));
}
__device__ __forceinline__ float lse3b(float a, float b) {   // LSE(a,b,0)
    float m = fmaxf(fmaxf(a, b), 0.f);
    return m + lg2a(ex2a(a - m) + ex2a(b - m) + ex2a(-m));
}

// ================= norms =================
__global__ void norm_kernel(const float* __restrict__ x, const float* __restrict__ y) {
    int w = (blockIdx.x * blockDim.x + threadIdx.x) >> 5;
    int lane = threadIdx.x & 31;
    #pragma unroll
    for (int s = 0; s < 16; s++) {
        int row = w + s * 256;
        const float* p = (row < 2048) ? (x + row * 128) : (y + (row - 2048) * 128);
        float v0 = p[lane], v1 = p[lane + 32], v2 = p[lane + 64], v3 = p[lane + 96];
        float sum = v0 * v0 + v1 * v1 + v2 * v2 + v3 * v3;
        #pragma unroll
        for (int o = 16; o > 0; o >>= 1) sum += __shfl_xor_sync(0xffffffffu, sum, o);
        if (lane == 0) g_n2[row] = sum;
    }
}

// ================= S = x2 + y2 - 2 x.y  (64x64 tiles) =================
__global__ void __launch_bounds__(256) dist_kernel(const float* __restrict__ x,
                                                   const float* __restrict__ y) {
    int b = blockIdx.z;
    int i0 = blockIdx.y * 64, j0 = blockIdx.x * 64;
    const float* xb = x + (b * 512 + i0) * 128;
    const float* yb = y + (b * 512 + j0) * 128;
    __shared__ float xs[16][64];
    __shared__ float ys[16][64];
    int tid = threadIdx.x;
    int tx = tid & 15, ty = tid >> 4;
    float acc[4][4];
    #pragma unroll
    for (int r = 0; r < 4; r++)
        #pragma unroll
        for (int c = 0; c < 4; c++) acc[r][c] = 0.f;

    for (int kc = 0; kc < 128; kc += 16) {
        __syncthreads();
        #pragma unroll
        for (int l = 0; l < 4; l++) {
            int e = tid + l * 256;
            int r = e >> 4, kk = e & 15;
            xs[kk][r] = xb[r * 128 + kc + kk];
            ys[kk][r] = yb[r * 128 + kc + kk];
        }
        __syncthreads();
        #pragma unroll
        for (int kk = 0; kk < 16; kk++) {
            float4 a  = *(const float4*)&xs[kk][ty * 4];
            float4 bv = *(const float4*)&ys[kk][tx * 4];
            float ar[4] = {a.x, a.y, a.z, a.w};
            float br[4] = {bv.x, bv.y, bv.z, bv.w};
            #pragma unroll
            for (int r = 0; r < 4; r++)
                #pragma unroll
                for (int c = 0; c < 4; c++)
                    acc[r][c] = fmaf(ar[r], br[c], acc[r][c]);
        }
    }
    float x2[4], y2[4];
    #pragma unroll
    for (int r = 0; r < 4; r++) x2[r] = g_n2[b * 512 + i0 + ty * 4 + r];
    #pragma unroll
    for (int c = 0; c < 4; c++) y2[c] = g_n2[2048 + b * 512 + j0 + tx * 4 + c];
    float* Sb = g_S + b * 262144;
    #pragma unroll
    for (int r = 0; r < 4; r++) {
        float4 o;
        o.x = x2[r] + y2[0] - 2.f * acc[r][0];
        o.y = x2[r] + y2[1] - 2.f * acc[r][1];
        o.z = x2[r] + y2[2] - 2.f * acc[r][2];
        o.w = x2[r] + y2[3] - 2.f * acc[r][3];
        *(float4*)&Sb[(i0 + ty * 4 + r) * 512 + j0 + tx * 4] = o;
    }
}

// ================= reskew: M[512][512] -> F4[u][t][q], base-2 scaled ============
// F[u][t][q] = LOG2E * M[2(u-t) + (q>>1)][2t + (q&1)]  if 0 <= u-t < 256, else 0
__global__ void __launch_bounds__(256) reskew_kernel(const float* __restrict__ go,
                                                     const float* __restrict__ ge) {
    int m = blockIdx.y;                 // 0..3 = S batches, 4 = go, 5 = ge
    int ut = blockIdx.x >> 3;           // 16 u-tiles of 32
    int jt = blockIdx.x & 7;            // 8 t-tiles of 32
    const float* src = (m < 4) ? (g_S + m * 262144) : ((m == 4) ? go : ge);
    float* dst = (m < 4) ? (float*)(g_Sf4 + m * (FU * 256)) :
                 ((m == 4) ? (float*)g_gof4 : (float*)g_gef4);
    int u0 = ut * 32, t0 = jt * 32;
    int rbase = 2 * (u0 - t0) - 62;     // 126 src rows
    int cbase = 2 * t0;                 // 64 src cols
    __shared__ float sm[126 * 65];
    int tid = threadIdx.x;
    #pragma unroll
    for (int l = 0; l < 32; l++) {
        int e = tid + l * 256;
        if (e < 126 * 64) {
            int rr = e >> 6, cc = e & 63;
            int gr = rbase + rr;
            sm[rr * 65 + cc] = (gr >= 0 && gr < 512) ?
                LOG2E * src[gr * 512 + cbase + cc] : 0.f;
        }
    }
    __syncthreads();
    #pragma unroll
    for (int l = 0; l < 16; l++) {
        int e = tid + l * 256;           // 4096 dst elements
        int q = e & 3, tr = (e >> 2) & 31, ur = e >> 7;
        int u = u0 + ur, t = t0 + tr;
        int dq = u - t;
        float v = 0.f;
        if (dq >= 0 && dq < 256) {
            int rr = 2 * (ur - tr) + (q >> 1) + 62;
            v = sm[rr * 65 + 2 * tr + (q & 1)];
        }
        dst[(u * 256 + t) * 4 + q] = v;
    }
}

// ================= wavefront soft-SW; cluster of 2 CTAs per batch ===============
__global__ __launch_bounds__(SWT, 1) __cluster_dims__(2, 1, 1)
void sw_kernel() {
    const int c = blockIdx.x;          // rank in cluster: 0 = left cols, 1 = right
    const int b = blockIdx.y;
    const int t = threadIdx.x, lane = t & 31, warp = t >> 5;
    const int tg = c * 128 + t;        // global thread slot (0..255)
    const float4* S4  = g_Sf4 + b * (FU * 256);
    const float4* go4 = g_gof4;
    const float4* ge4 = g_gef4;
    float4* Df4 = g_Df4 + b * (FU * 256);

    __shared__ float sh[2][4][8];      // [parity][warp][Dlo,Ixlo,glo,Dhi,Ixhi,ghi,pad,pad]
    __shared__ __align__(16) float ring[512 * 8];   // boundary ring (used in CTA1)
    __shared__ int flag;

    unsigned int ringLocal = (unsigned int)__cvta_generic_to_shared(ring);
    unsigned int flagLocal = (unsigned int)__cvta_generic_to_shared(&flag);
    unsigned int ringPeer, flagPeer;
    asm("mapa.shared::cluster.u32 %0, %1, %2;" : "=r"(ringPeer) : "r"(ringLocal), "r"(1));
    asm("mapa.shared::cluster.u32 %0, %1, %2;" : "=r"(flagPeer) : "r"(flagLocal), "r"(1));

    if (t < 64) {
        int q = t & 7;
        ((float*)sh)[t] = (q == 2 || q == 5) ? 0.f : NEGV;
    }
    if (t == 0) flag = -1;
    __syncthreads();
    asm volatile("barrier.cluster.arrive.aligned;" ::: "memory");
    asm volatile("barrier.cluster.wait.aligned;" ::: "memory");

    // carried state (previous superstep's hi row of own columns)
    float hA = NEGV, IyA = NEGV, gA = 0.f;
    float hB = NEGV, IyB = NEGV;
    float BDlo = NEGV, BIlo = NEGV, Bglo = 0.f;
    float BDhi = NEGV, BIhi = NEGV, Bghi = 0.f;
    float gstale = 0.f;

    const int base = c * 128;          // first step for this CTA
    float4 sP = S4[base * 256 + tg], goP = go4[base * 256 + tg], geP = ge4[base * 256 + tg];

    auto step = [&](int u, int par) {
        float4 sC = sP, goC = goP, geC = geP;
        {
            int idx = (u + 1) * 256 + tg;
            sP = S4[idx]; goP = go4[idx]; geP = ge4[idx];
        }
        float nDlo = __shfl_up_sync(0xffffffffu, BDlo, 1);
        float nIlo = __shfl_up_sync(0xffffffffu, BIlo, 1);
        float nglo = __shfl_up_sync(0xffffffffu, Bglo, 1);
        float nDhi = __shfl_up_sync(0xffffffffu, BDhi, 1);
        float nIhi = __shfl_up_sync(0xffffffffu, BIhi, 1);
        float nghi = __shfl_up_sync(0xffffffffu, Bghi, 1);
        if (warp > 0) {
            int pp = par ^ 1;
            int wsel = warp - 1;
            float sD0 = sh[pp][wsel][0], sI0 = sh[pp][wsel][1], sg0 = sh[pp][wsel][2];
            float sD1 = sh[pp][wsel][3], sI1 = sh[pp][wsel][4], sg1 = sh[pp][wsel][5];
            if (lane == 0) {
                nDlo = sD0; nIlo = sI0; nglo = sg0;
                nDhi = sD1; nIhi = sI1; nghi = sg1;
            }
        } else if (c == 0) {
            if (lane == 0) {
                nDlo = NEGV; nIlo = NEGV; nglo = 0.f;
                nDhi = NEGV; nIhi = NEGV; nghi = 0.f;
            }
        } else if (u <= 383) {
            // warp 0 of CTA1: boundary from CTA0 via ring[u-1]
            int need = u - 1;
            int fv;
            do {
                asm volatile("ld.acquire.cluster.shared::cta.b32 %0, [%1];"
                             : "=r"(fv) : "r"(flagLocal));
            } while (fv < need);
            float4 r0 = *(const float4*)&ring[need * 8];
            float4 r1 = *(const float4*)&ring[need * 8 + 4];
            if (lane == 0) {
                nDlo = r0.x; nIlo = r0.y; nglo = r0.z;
                nDhi = r0.w; nIhi = r1.x; nghi = r1.y;
            }
        }

        bool act = (u >= tg) && (u - tg < 256);
        if (act) {
            float ix1 = lse2b(nDlo - goC.x, nIlo - geC.x);
            float iy1 = lse2b(hA - goC.x, IyA - geC.x);
            float d1  = sC.x + gstale;
            float h1  = lse2b(d1, ix1);
            float g1  = lse3b(h1, iy1);

            float ix2 = lse2b(d1 - goC.y, ix1 - geC.y);
            float iy2 = lse2b(hB - goC.y, IyB - geC.y);
            float d2  = sC.y + gA;
            float h2  = lse2b(d2, ix2);
            float g2  = lse3b(h2, iy2);

            float ix3 = lse2b(nDhi - goC.z, nIhi - geC.z);
            float iy3 = lse2b(h1 - goC.z, iy1 - geC.z);
            float d3  = sC.z + nglo;
            float h3  = lse2b(d3, ix3);
            float g3  = lse3b(h3, iy3);

            float ix4 = lse2b(d3 - goC.w, ix3 - geC.w);
            float iy4 = lse2b(h2 - goC.w, iy2 - geC.w);
            float d4  = sC.w + g1;
            float h4  = lse2b(d4, ix4);
            float g4  = lse3b(h4, iy4);

            Df4[u * 256 + tg] = make_float4(d1, d2, d3, d4);

            hA = h3; IyA = iy3; gA = g3;
            hB = h4; IyB = iy4;
            BDlo = d2; BIlo = ix2; Bglo = g2;
            BDhi = d4; BIhi = ix4; Bghi = g4;

            if (c == 0 && t == 127) {
                // push boundary values to CTA1's ring[u], then release the flag
                asm volatile("st.shared::cluster.v4.f32 [%0], {%1,%2,%3,%4};"
                    :: "r"(ringPeer + (unsigned int)u * 32u),
                       "f"(BDlo), "f"(BIlo), "f"(Bglo), "f"(BDhi));
                asm volatile("st.shared::cluster.v4.f32 [%0], {%1,%2,%3,%4};"
                    :: "r"(ringPeer + (unsigned int)u * 32u + 16u),
                       "f"(BIhi), "f"(Bghi), "f"(Bghi), "f"(Bghi));
                asm volatile("st.release.cluster.shared::cluster.b32 [%0], %1;"
                    :: "r"(flagPeer), "r"(u));
            }
        }
        gstale = nghi;
        if (lane == 31) {
            sh[par][warp][0] = BDlo; sh[par][warp][1] = BIlo; sh[par][warp][2] = Bglo;
            sh[par][warp][3] = BDhi; sh[par][warp][4] = BIhi; sh[par][warp][5] = Bghi;
        }
        __syncthreads();
    };

    for (int i = 0; i < 382; i += 2) {
        step(base + i, 0);
        step(base + i + 1, 1);
    }
    step(base + 382, 0);

    asm volatile("barrier.cluster.arrive.aligned;" ::: "memory");
    asm volatile("barrier.cluster.wait.aligned;" ::: "memory");
}

// ================= LSE over valid D slots (base-2 domain) =================
__global__ void lse_part() {
    int blk = blockIdx.x, b = blockIdx.y;    // 64 x 4
    const float4* Dv = g_Df4 + b * (FU * 256);
    int tid = threadIdx.x;
    float m = NEGV, s = 0.f;
    #pragma unroll
    for (int l = 0; l < 8; l++) {
        int slot = blk * 2048 + tid + l * 256;
        int u = slot >> 8, tc = slot & 255;
        int dq = u - tc;
        if (dq >= 0 && dq < 256) {
            float4 v = Dv[slot];
            float m4 = fmaxf(fmaxf(v.x, v.y), fmaxf(v.z, v.w));
            float nm = fmaxf(m, m4);
            s = s * ex2a(m - nm) + ex2a(v.x - nm) + ex2a(v.y - nm)
                                 + ex2a(v.z - nm) + ex2a(v.w - nm);
            m = nm;
        }
    }
    __shared__ float sm[256], ss[256];
    sm[tid] = m; ss[tid] = s;
    __syncthreads();
    for (int o = 128; o > 0; o >>= 1) {
        if (tid < o) {
            float m2 = sm[tid + o], s2 = ss[tid + o];
            float nm = fmaxf(sm[tid], m2);
            ss[tid] = ss[tid] * ex2a(sm[tid] - nm) + s2 * ex2a(m2 - nm);
            sm[tid] = nm;
        }
        __syncthreads();
    }
    if (tid == 0) { g_pm[b * 64 + blk] = sm[0]; g_ps[b * 64 + blk] = ss[0]; }
}

__global__ void lse_final(float* __restrict__ out) {
    int t = threadIdx.x;              // 256
    int b = t >> 6, r = t & 63;
    __shared__ float sm[256], ss[256], vv[4];
    sm[t] = g_pm[b * 64 + r]; ss[t] = g_ps[b * 64 + r];
    __syncthreads();
    for (int o = 32; o > 0; o >>= 1) {
        if (r < o) {
            float m2 = sm[t + o], s2 = ss[t + o];
            float nm = fmaxf(sm[t], m2);
            ss[t] = ss[t] * ex2a(sm[t] - nm) + s2 * ex2a(m2 - nm);
            sm[t] = nm;
        }
        __syncthreads();
    }
    if (r == 0) vv[b] = LN2 * (sm[t] + lg2a(ss[t]));
    __syncthreads();
    if (t == 0) out[0] = 0.25f * (vv[0] + vv[1] + vv[2] + vv[3]);
}

// ================= deskew: probas[r][j] = LN2 * Df4[t+(r>>1)][t=j>>1].q ==========
__global__ void __launch_bounds__(256) deskew_kernel(float* __restrict__ out) {
    int b = blockIdx.y;
    const float* Df = (const float*)(g_Df4 + b * (FU * 256));
    float* ob = out + 1 + b * 262144;
    int e0 = blockIdx.x * 256 + threadIdx.x;     // 128 blocks
    #pragma unroll
    for (int l = 0; l < 8; l++) {
        int e = e0 + l * 32768;
        int r = e >> 9, j = e & 511;
        int tc = j >> 1;
        int u = tc + (r >> 1);
        int q = ((r & 1) << 1) | (j & 1);
        ob[e] = LN2 * Df[(u * 256 + tc) * 4 + q];
    }
}

// ================= launcher =================
extern "C" void kernel_launch(void* const* d_in, const int* in_sizes, int n_in,
                              void* d_out, int out_size) {
    const float* x  = (const float*)d_in[0];
    const float* y  = (const float*)d_in[1];
    const float* go = (const float*)d_in[2];
    const float* ge = (const float*)d_in[3];
    float* out = (float*)d_out;

    norm_kernel<<<32, 256>>>(x, y);
    dist_kernel<<<dim3(8, 8, 4), 256>>>(x, y);
    reskew_kernel<<<dim3(128, 6), 256>>>(go, ge);
    sw_kernel<<<dim3(2, 4), SWT>>>();
    lse_part<<<dim3(64, 4), 256>>>();
    deskew_kernel<<<dim3(128, 4), 256>>>(out);
    lse_final<<<1, 256>>>(out);
}

// round 12
// speedup vs baseline: 1.0592x; 1.0592x over previous
#include <cuda_runtime.h>
#include <stdint.h>
#include <math.h>

#define NEGV  -1e30f
#define SWT   128         // sw threads; each owns col-pairs t and t+128
#define STEPS 639         // 2*256 pass-steps + 127 skew
#define FUU   640         // feed u-rows
#define LOG2E 1.4426950408889634f
#define LN2   0.6931471805599453f

// ---- static device scratch ----
__device__ float  g_S[4 * 512 * 512];          // plain score matrices
__device__ float  g_n2[2 * 4 * 512];           // row norms
__device__ float4 g_Sf4[4 * FUU * 128];        // skewed S feed (base-2 scaled)
__device__ float4 g_gof4[FUU * 128];           // skewed go feed
__device__ float4 g_gef4[FUU * 128];           // skewed ge feed
__device__ float4 g_Df4[4 * FUU * 128];        // skewed D output (base-2 domain)
__device__ float  g_pm[256], g_ps[256];        // LSE partials (40 per batch)

__device__ __forceinline__ float ex2a(float x) {
    float r; asm("ex2.approx.ftz.f32 %0, %1;" : "=f"(r) : "f"(x)); return r;
}
__device__ __forceinline__ float lg2a(float x) {
    float r; asm("lg2.approx.ftz.f32 %0, %1;" : "=f"(r) : "f"(x)); return r;
}
__device__ __forceinline__ float lse2b(float a, float b) {
    float m = fmaxf(a, b), n = fminf(a, b);
    return m + lg2a(1.0f + ex2a(n - m));
}
__device__ __forceinline__ float lse3b(float a, float b) {   // LSE(a,b,0)
    float m = fmaxf(fmaxf(a, b), 0.f);
    return m + lg2a(ex2a(a - m) + ex2a(b - m) + ex2a(-m));
}

// ================= norms =================
__global__ void norm_kernel(const float* __restrict__ x, const float* __restrict__ y) {
    int w = (blockIdx.x * blockDim.x + threadIdx.x) >> 5;
    int lane = threadIdx.x & 31;
    #pragma unroll
    for (int s = 0; s < 16; s++) {
        int row = w + s * 256;
        const float* p = (row < 2048) ? (x + row * 128) : (y + (row - 2048) * 128);
        float v0 = p[lane], v1 = p[lane + 32], v2 = p[lane + 64], v3 = p[lane + 96];
        float sum = v0 * v0 + v1 * v1 + v2 * v2 + v3 * v3;
        #pragma unroll
        for (int o = 16; o > 0; o >>= 1) sum += __shfl_xor_sync(0xffffffffu, sum, o);
        if (lane == 0) g_n2[row] = sum;
    }
}

// ================= S = x2 + y2 - 2 x.y  (64x64 tiles) =================
__global__ void __launch_bounds__(256) dist_kernel(const float* __restrict__ x,
                                                   const float* __restrict__ y) {
    int b = blockIdx.z;
    int i0 = blockIdx.y * 64, j0 = blockIdx.x * 64;
    const float* xb = x + (b * 512 + i0) * 128;
    const float* yb = y + (b * 512 + j0) * 128;
    __shared__ float xs[16][64];
    __shared__ float ys[16][64];
    int tid = threadIdx.x;
    int tx = tid & 15, ty = tid >> 4;
    float acc[4][4];
    #pragma unroll
    for (int r = 0; r < 4; r++)
        #pragma unroll
        for (int c = 0; c < 4; c++) acc[r][c] = 0.f;

    for (int kc = 0; kc < 128; kc += 16) {
        __syncthreads();
        #pragma unroll
        for (int l = 0; l < 4; l++) {
            int e = tid + l * 256;
            int r = e >> 4, kk = e & 15;
            xs[kk][r] = xb[r * 128 + kc + kk];
            ys[kk][r] = yb[r * 128 + kc + kk];
        }
        __syncthreads();
        #pragma unroll
        for (int kk = 0; kk < 16; kk++) {
            float4 a  = *(const float4*)&xs[kk][ty * 4];
            float4 bv = *(const float4*)&ys[kk][tx * 4];
            float ar[4] = {a.x, a.y, a.z, a.w};
            float br[4] = {bv.x, bv.y, bv.z, bv.w};
            #pragma unroll
            for (int r = 0; r < 4; r++)
                #pragma unroll
                for (int c = 0; c < 4; c++)
                    acc[r][c] = fmaf(ar[r], br[c], acc[r][c]);
        }
    }
    float x2[4], y2[4];
    #pragma unroll
    for (int r = 0; r < 4; r++) x2[r] = g_n2[b * 512 + i0 + ty * 4 + r];
    #pragma unroll
    for (int c = 0; c < 4; c++) y2[c] = g_n2[2048 + b * 512 + j0 + tx * 4 + c];
    float* Sb = g_S + b * 262144;
    #pragma unroll
    for (int r = 0; r < 4; r++) {
        float4 o;
        o.x = x2[r] + y2[0] - 2.f * acc[r][0];
        o.y = x2[r] + y2[1] - 2.f * acc[r][1];
        o.z = x2[r] + y2[2] - 2.f * acc[r][2];
        o.w = x2[r] + y2[3] - 2.f * acc[r][3];
        *(float4*)&Sb[(i0 + ty * 4 + r) * 512 + j0 + tx * 4] = o;
    }
}

// ================= reskew: M -> F[u][t][q] for striped 2-pass layout ============
// d=u-t, k=d>>8, s=d&255; F = LOG2E*M[2s+(q>>1)][2(t+128k)+(q&1)], valid 0<=d<512.
// Tiles along constant-d diagonals so k is uniform per tile.
__global__ void __launch_bounds__(256) reskew_kernel(const float* __restrict__ go,
                                                     const float* __restrict__ ge) {
    int m = blockIdx.y;                 // 0..3 = S batches, 4 = go, 5 = ge
    int dt = blockIdx.x >> 2;           // 8 d-tiles of 64
    int tt = blockIdx.x & 3;            // 4 t-tiles of 32
    const float* src = (m < 4) ? (g_S + m * 262144) : ((m == 4) ? go : ge);
    float* dst = (m < 4) ? (float*)(g_Sf4 + m * (FUU * 128)) :
                 ((m == 4) ? (float*)g_gof4 : (float*)g_gef4);
    int d0 = dt * 64, t0 = tt * 32;
    int k = d0 >> 8, s0 = d0 & 255;
    int r0 = 2 * s0;                    // 128 rows
    int c0 = 2 * (t0 + 128 * k);        // 64 cols
    __shared__ float sm[128][65];
    int tid = threadIdx.x;
    #pragma unroll
    for (int l = 0; l < 32; l++) {
        int e = tid + l * 256;
        int rr = e >> 6, cc = e & 63;
        sm[rr][cc] = LOG2E * src[(r0 + rr) * 512 + c0 + cc];
    }
    __syncthreads();
    #pragma unroll
    for (int l = 0; l < 32; l++) {
        int e = tid + l * 256;          // 8192 dst elements
        int q = e & 3, tl = (e >> 2) & 31, dd = e >> 7;
        int u = d0 + dd + t0 + tl;
        dst[(u * 128 + t0 + tl) * 4 + q] = sm[2 * dd + (q >> 1)][2 * tl + (q & 1)];
    }
}

// ================= wavefront soft-SW; striped 2-pass, 1 CTA/batch ===============
__global__ __launch_bounds__(SWT, 1) void sw_kernel() {
    const int b = blockIdx.x;
    const int t = threadIdx.x, lane = t & 31, warp = t >> 5;
    const float4* S4  = g_Sf4 + b * (FUU * 128);
    const float4* go4 = g_gof4;
    const float4* ge4 = g_gef4;
    float4* Df4 = g_Df4 + b * (FUU * 128);

    __shared__ float sh[2][4][8];       // [parity][warp][Dlo,Ixlo,glo,Dhi,Ixhi,ghi,pad,pad]
    __shared__ float ring[256][8];      // pass-0 boundary history (pair 127)

    if (t < 64) {
        int q = t & 7;
        ((float*)sh)[t] = (q == 2 || q == 5) ? 0.f : NEGV;
    }
    __syncthreads();

    float hA = NEGV, IyA = NEGV, gA = 0.f;
    float hB = NEGV, IyB = NEGV;
    float BDlo = NEGV, BIlo = NEGV, Bglo = 0.f;
    float BDhi = NEGV, BIhi = NEGV, Bghi = 0.f;
    float gstale = 0.f;

    float4 sP = S4[t], goP = go4[t], geP = ge4[t];

    auto step = [&](int u, int par) {
        float4 sC = sP, goC = goP, geC = geP;
        {
            int idx = (u + 1) * 128 + t;
            sP = S4[idx]; goP = go4[idx]; geP = ge4[idx];
        }
        int d = u - t;
        float nDlo = __shfl_up_sync(0xffffffffu, BDlo, 1);
        float nIlo = __shfl_up_sync(0xffffffffu, BIlo, 1);
        float nglo = __shfl_up_sync(0xffffffffu, Bglo, 1);
        float nDhi = __shfl_up_sync(0xffffffffu, BDhi, 1);
        float nIhi = __shfl_up_sync(0xffffffffu, BIhi, 1);
        float nghi = __shfl_up_sync(0xffffffffu, Bghi, 1);
        if (lane == 0) {
            if (warp > 0) {
                int pp = par ^ 1;
                nDlo = sh[pp][warp - 1][0]; nIlo = sh[pp][warp - 1][1];
                nglo = sh[pp][warp - 1][2]; nDhi = sh[pp][warp - 1][3];
                nIhi = sh[pp][warp - 1][4]; nghi = sh[pp][warp - 1][5];
            } else if (d >= 256 && d < 512) {
                // thread 0 pass 1: left neighbor = pair 127 pass-0 history
                int s = d - 256;
                nDlo = ring[s][0]; nIlo = ring[s][1]; nglo = ring[s][2];
                nDhi = ring[s][3]; nIhi = ring[s][4]; nghi = ring[s][5];
            } else {
                nDlo = NEGV; nIlo = NEGV; nglo = 0.f;
                nDhi = NEGV; nIhi = NEGV; nghi = 0.f;
            }
        }
        if (d == 256) {   // pass boundary: new column starts at row 0
            hA = NEGV; IyA = NEGV; gA = 0.f;
            hB = NEGV; IyB = NEGV;
            gstale = 0.f;
        }
        bool act = (d >= 0) && (d < 512);
        if (act) {
            float ix1 = lse2b(nDlo - goC.x, nIlo - geC.x);
            float iy1 = lse2b(hA - goC.x, IyA - geC.x);
            float d1  = sC.x + gstale;
            float h1  = lse2b(d1, ix1);
            float g1  = lse3b(h1, iy1);

            float ix2 = lse2b(d1 - goC.y, ix1 - geC.y);
            float iy2 = lse2b(hB - goC.y, IyB - geC.y);
            float d2  = sC.y + gA;
            float h2  = lse2b(d2, ix2);
            float g2  = lse3b(h2, iy2);

            float ix3 = lse2b(nDhi - goC.z, nIhi - geC.z);
            float iy3 = lse2b(h1 - goC.z, iy1 - geC.z);
            float d3  = sC.z + nglo;
            float h3  = lse2b(d3, ix3);
            float g3  = lse3b(h3, iy3);

            float ix4 = lse2b(d3 - goC.w, ix3 - geC.w);
            float iy4 = lse2b(h2 - goC.w, iy2 - geC.w);
            float d4  = sC.w + g1;
            float h4  = lse2b(d4, ix4);
            float g4  = lse3b(h4, iy4);

            Df4[u * 128 + t] = make_float4(d1, d2, d3, d4);

            hA = h3; IyA = iy3; gA = g3;
            hB = h4; IyB = iy4;
            BDlo = d2; BIlo = ix2; Bglo = g2;
            BDhi = d4; BIhi = ix4; Bghi = g4;

            if (t == 127 && d < 256) {       // publish pass-0 boundary history
                ring[d][0] = BDlo; ring[d][1] = BIlo; ring[d][2] = Bglo;
                ring[d][3] = BDhi; ring[d][4] = BIhi; ring[d][5] = Bghi;
            }
        }
        gstale = nghi;
        if (lane == 31) {
            sh[par][warp][0] = BDlo; sh[par][warp][1] = BIlo; sh[par][warp][2] = Bglo;
            sh[par][warp][3] = BDhi; sh[par][warp][4] = BIhi; sh[par][warp][5] = Bghi;
        }
        __syncthreads();
    };

    for (int i = 0; i < 638; i += 2) {
        step(i, 0);
        step(i + 1, 1);
    }
    step(638, 0);
}

// ================= LSE over valid D slots (base-2 domain) =================
__global__ void lse_part() {
    int blk = blockIdx.x, b = blockIdx.y;    // 40 x 4
    const float4* Dv = g_Df4 + b * (FUU * 128);
    int tid = threadIdx.x;
    float m = NEGV, s = 0.f;
    #pragma unroll
    for (int l = 0; l < 8; l++) {
        int slot = blk * 2048 + tid + l * 256;    // 40*2048 = 81920 = 640*128
        int u = slot >> 7, tc = slot & 127;
        int d = u - tc;
        if (d >= 0 && d < 512) {
            float4 v = Dv[slot];
            float m4 = fmaxf(fmaxf(v.x, v.y), fmaxf(v.z, v.w));
            float nm = fmaxf(m, m4);
            s = s * ex2a(m - nm) + ex2a(v.x - nm) + ex2a(v.y - nm)
                                 + ex2a(v.z - nm) + ex2a(v.w - nm);
            m = nm;
        }
    }
    __shared__ float sm[256], ss[256];
    sm[tid] = m; ss[tid] = s;
    __syncthreads();
    for (int o = 128; o > 0; o >>= 1) {
        if (tid < o) {
            float m2 = sm[tid + o], s2 = ss[tid + o];
            float nm = fmaxf(sm[tid], m2);
            ss[tid] = ss[tid] * ex2a(sm[tid] - nm) + s2 * ex2a(m2 - nm);
            sm[tid] = nm;
        }
        __syncthreads();
    }
    if (tid == 0) { g_pm[b * 64 + blk] = sm[0]; g_ps[b * 64 + blk] = ss[0]; }
}

__global__ void lse_final(float* __restrict__ out) {
    int t = threadIdx.x;              // 256
    int b = t >> 6, r = t & 63;
    float m = (r < 40) ? g_pm[b * 64 + r] : NEGV;
    float s = (r < 40) ? g_ps[b * 64 + r] : 0.f;
    __shared__ float sm[256], ss[256], vv[4];
    sm[t] = m; ss[t] = s;
    __syncthreads();
    for (int o = 32; o > 0; o >>= 1) {
        if (r < o) {
            float m2 = sm[t + o], s2 = ss[t + o];
            float nm = fmaxf(sm[t], m2);
            ss[t] = ss[t] * ex2a(sm[t] - nm) + s2 * ex2a(m2 - nm);
            sm[t] = nm;
        }
        __syncthreads();
    }
    if (r == 0) vv[b] = LN2 * (sm[t] + lg2a(ss[t]));
    __syncthreads();
    if (t == 0) out[0] = 0.25f * (vv[0] + vv[1] + vv[2] + vv[3]);
}

// ================= deskew: Df[u][t][q] -> probas, inverse of reskew mapping =====
__global__ void __launch_bounds__(256) deskew_kernel(float* __restrict__ out) {
    int b = blockIdx.y;
    int dt = blockIdx.x >> 2, tt = blockIdx.x & 3;
    const float* Df = (const float*)(g_Df4 + b * (FUU * 128));
    int d0 = dt * 64, t0 = tt * 32;
    int k = d0 >> 8, s0 = d0 & 255;
    int r0 = 2 * s0, c0 = 2 * (t0 + 128 * k);
    __shared__ float sm[128][65];
    int tid = threadIdx.x;
    #pragma unroll
    for (int l = 0; l < 32; l++) {
        int e = tid + l * 256;
        int q = e & 3, tl = (e >> 2) & 31, dd = e >> 7;
        int u = d0 + dd + t0 + tl;
        sm[2 * dd + (q >> 1)][2 * tl + (q & 1)] = Df[(u * 128 + t0 + tl) * 4 + q];
    }
    __syncthreads();
    float* ob = out + 1 + b * 262144;
    #pragma unroll
    for (int l = 0; l < 32; l++) {
        int e = tid + l * 256;
        int rr = e >> 6, cc = e & 63;
        ob[(r0 + rr) * 512 + c0 + cc] = LN2 * sm[rr][cc];
    }
}

// ================= launcher =================
extern "C" void kernel_launch(void* const* d_in, const int* in_sizes, int n_in,
                              void* d_out, int out_size) {
    const float* x  = (const float*)d_in[0];
    const float* y  = (const float*)d_in[1];
    const float* go = (const float*)d_in[2];
    const float* ge = (const float*)d_in[3];
    float* out = (float*)d_out;

    norm_kernel<<<32, 256>>>(x, y);
    dist_kernel<<<dim3(8, 8, 4), 256>>>(x, y);
    reskew_kernel<<<dim3(32, 6), 256>>>(go, ge);
    sw_kernel<<<4, SWT>>>();
    lse_part<<<dim3(40, 4), 256>>>();
    deskew_kernel<<<dim3(32, 4), 256>>>(out);
    lse_final<<<1, 256>>>(out);
}

// round 13
// speedup vs baseline: 1.3515x; 1.2760x over previous
#include <cuda_runtime.h>
#include <stdint.h>
#include <math.h>

#define NEGV  -1e30f
#define SWT   128         // sw threads; thread owns 4 cols, 2 rows per step
#define STEPS 383         // 256 row-groups + 127 skew
#define FUU   384         // feed u-rows (STEPS + 1 prefetch)
#define LOG2E 1.4426950408889634f
#define LN2   0.6931471805599453f

// ---- static device scratch ----
__device__ float  g_S[4 * 512 * 512];          // plain score matrices
__device__ float  g_n2[2 * 4 * 512];           // row norms
__device__ float4 g_Sf4[4 * FUU * 256];        // skewed S feed   [u][t][r] (base-2)
__device__ float4 g_gof4[FUU * 256];           // skewed go feed
__device__ float4 g_gef4[FUU * 256];           // skewed ge feed
__device__ float4 g_Df4[4 * FUU * 256];        // skewed D output [u][t][r]
__device__ float  g_pm[256], g_ps[256];        // LSE partials (48 per batch)

__device__ __forceinline__ float ex2a(float x) {
    float r; asm("ex2.approx.ftz.f32 %0, %1;" : "=f"(r) : "f"(x)); return r;
}
__device__ __forceinline__ float lg2a(float x) {
    float r; asm("lg2.approx.ftz.f32 %0, %1;" : "=f"(r) : "f"(x)); return r;
}
__device__ __forceinline__ float lse2b(float a, float b) {
    float m = fmaxf(a, b), n = fminf(a, b);
    return m + lg2a(1.0f + ex2a(n - m));
}
__device__ __forceinline__ float lse3b(float a, float b) {   // LSE(a,b,0)
    float m = fmaxf(fmaxf(a, b), 0.f);
    return m + lg2a(ex2a(a - m) + ex2a(b - m) + ex2a(-m));
}

// ================= norms =================
__global__ void norm_kernel(const float* __restrict__ x, const float* __restrict__ y) {
    int w = (blockIdx.x * blockDim.x + threadIdx.x) >> 5;
    int lane = threadIdx.x & 31;
    #pragma unroll
    for (int s = 0; s < 16; s++) {
        int row = w + s * 256;
        const float* p = (row < 2048) ? (x + row * 128) : (y + (row - 2048) * 128);
        float v0 = p[lane], v1 = p[lane + 32], v2 = p[lane + 64], v3 = p[lane + 96];
        float sum = v0 * v0 + v1 * v1 + v2 * v2 + v3 * v3;
        #pragma unroll
        for (int o = 16; o > 0; o >>= 1) sum += __shfl_xor_sync(0xffffffffu, sum, o);
        if (lane == 0) g_n2[row] = sum;
    }
}

// ================= S = x2 + y2 - 2 x.y  (64x64 tiles) =================
__global__ void __launch_bounds__(256) dist_kernel(const float* __restrict__ x,
                                                   const float* __restrict__ y) {
    int b = blockIdx.z;
    int i0 = blockIdx.y * 64, j0 = blockIdx.x * 64;
    const float* xb = x + (b * 512 + i0) * 128;
    const float* yb = y + (b * 512 + j0) * 128;
    __shared__ float xs[16][64];
    __shared__ float ys[16][64];
    int tid = threadIdx.x;
    int tx = tid & 15, ty = tid >> 4;
    float acc[4][4];
    #pragma unroll
    for (int r = 0; r < 4; r++)
        #pragma unroll
        for (int c = 0; c < 4; c++) acc[r][c] = 0.f;

    for (int kc = 0; kc < 128; kc += 16) {
        __syncthreads();
        #pragma unroll
        for (int l = 0; l < 4; l++) {
            int e = tid + l * 256;
            int r = e >> 4, kk = e & 15;
            xs[kk][r] = xb[r * 128 + kc + kk];
            ys[kk][r] = yb[r * 128 + kc + kk];
        }
        __syncthreads();
        #pragma unroll
        for (int kk = 0; kk < 16; kk++) {
            float4 a  = *(const float4*)&xs[kk][ty * 4];
            float4 bv = *(const float4*)&ys[kk][tx * 4];
            float ar[4] = {a.x, a.y, a.z, a.w};
            float br[4] = {bv.x, bv.y, bv.z, bv.w};
            #pragma unroll
            for (int r = 0; r < 4; r++)
                #pragma unroll
                for (int c = 0; c < 4; c++)
                    acc[r][c] = fmaf(ar[r], br[c], acc[r][c]);
        }
    }
    float x2[4], y2[4];
    #pragma unroll
    for (int r = 0; r < 4; r++) x2[r] = g_n2[b * 512 + i0 + ty * 4 + r];
    #pragma unroll
    for (int c = 0; c < 4; c++) y2[c] = g_n2[2048 + b * 512 + j0 + tx * 4 + c];
    float* Sb = g_S + b * 262144;
    #pragma unroll
    for (int r = 0; r < 4; r++) {
        float4 o;
        o.x = x2[r] + y2[0] - 2.f * acc[r][0];
        o.y = x2[r] + y2[1] - 2.f * acc[r][1];
        o.z = x2[r] + y2[2] - 2.f * acc[r][2];
        o.w = x2[r] + y2[3] - 2.f * acc[r][3];
        *(float4*)&Sb[(i0 + ty * 4 + r) * 512 + j0 + tx * 4] = o;
    }
}

// ================= reskew: M -> F[u][t][r] (float4 over c), base-2 ==============
// element (u,t,r,c) = LOG2E * M[2(u-t)+r][4t+c], valid 0 <= u-t < 256.
// Tiles: d-tile 32 (8) x t-tile 32 (4); u = d0+dd + t0+tl.
__global__ void __launch_bounds__(256) reskew_kernel(const float* __restrict__ go,
                                                     const float* __restrict__ ge) {
    int m = blockIdx.y;                 // 0..3 = S batches, 4 = go, 5 = ge
    int dt = blockIdx.x >> 2;           // 0..7
    int tt = blockIdx.x & 3;            // 0..3
    const float* src = (m < 4) ? (g_S + m * 262144) : ((m == 4) ? go : ge);
    float4* dst = (m < 4) ? (g_Sf4 + m * (FUU * 256)) : ((m == 4) ? g_gof4 : g_gef4);
    int d0 = dt * 32, t0 = tt * 32;
    __shared__ __align__(16) float sm[64][132];
    int tid = threadIdx.x;
    #pragma unroll
    for (int l = 0; l < 32; l++) {
        int e = tid + l * 256;          // 8192 = 64 rows x 128 cols
        int rr = e >> 7, cc = e & 127;
        sm[rr][cc] = LOG2E * src[(2 * d0 + rr) * 512 + 4 * t0 + cc];
    }
    __syncthreads();
    #pragma unroll
    for (int l = 0; l < 8; l++) {
        int e = tid + l * 256;          // 2048 float4
        int r = e & 1, tl = (e >> 1) & 31, dd = e >> 6;
        int u = d0 + dd + t0 + tl;
        dst[(u * 128 + t0 + tl) * 2 + r] = *(const float4*)&sm[2 * dd + r][4 * tl];
    }
}

// ================= wavefront soft-SW; 1 CTA/batch, 4 cols x 2 rows/thread =======
__global__ __launch_bounds__(SWT, 1) void sw_kernel() {
    const int b = blockIdx.x;
    const int t = threadIdx.x, lane = t & 31, warp = t >> 5;
    const float4* S4  = g_Sf4 + b * (FUU * 256);
    const float4* go4 = g_gof4;
    const float4* ge4 = g_gef4;
    float4* Df4 = g_Df4 + b * (FUU * 256);

    __shared__ float sh[2][4][8];       // [parity][warp][BD0,BI0,Bg0,BD1,BI1,Bg1,pad,pad]
    if (t < 64) {
        int q = t & 7;
        ((float*)sh)[t] = (q == 2 || q == 5) ? 0.f : NEGV;
    }
    __syncthreads();

    // carried per-column state (prev step's hi row r1)
    float hS[4], IyS[4], gS[4];
    #pragma unroll
    for (int c = 0; c < 4; c++) { hS[c] = NEGV; IyS[c] = NEGV; gS[c] = 0.f; }
    // boundary (own col 3) per row
    float BD0 = NEGV, BI0 = NEGV, Bg0 = 0.f;
    float BD1 = NEGV, BI1 = NEGV, Bg1 = 0.f;
    float gstale = 0.f;

    int i0 = t * 2;
    float4 sP0 = S4[i0],  sP1 = S4[i0 + 1];
    float4 goP0 = go4[i0], goP1 = go4[i0 + 1];
    float4 geP0 = ge4[i0], geP1 = ge4[i0 + 1];

    auto step = [&](int u, int par) {
        float4 s0v = sP0, s1v = sP1, go0v = goP0, go1v = goP1, ge0v = geP0, ge1v = geP1;
        {
            int idx = ((u + 1) * 128 + t) * 2;
            sP0 = S4[idx];  sP1 = S4[idx + 1];
            goP0 = go4[idx]; goP1 = go4[idx + 1];
            geP0 = ge4[idx]; geP1 = ge4[idx + 1];
        }
        // neighbor exchange (col 4t-1, rows 2d and 2d+1)
        float nD0 = __shfl_up_sync(0xffffffffu, BD0, 1);
        float nI0 = __shfl_up_sync(0xffffffffu, BI0, 1);
        float ng0 = __shfl_up_sync(0xffffffffu, Bg0, 1);
        float nD1 = __shfl_up_sync(0xffffffffu, BD1, 1);
        float nI1 = __shfl_up_sync(0xffffffffu, BI1, 1);
        float ng1 = __shfl_up_sync(0xffffffffu, Bg1, 1);
        if (lane == 0) {
            if (warp > 0) {
                int pp = par ^ 1;
                nD0 = sh[pp][warp - 1][0]; nI0 = sh[pp][warp - 1][1]; ng0 = sh[pp][warp - 1][2];
                nD1 = sh[pp][warp - 1][3]; nI1 = sh[pp][warp - 1][4]; ng1 = sh[pp][warp - 1][5];
            } else {
                nD0 = NEGV; nI0 = NEGV; ng0 = 0.f;
                nD1 = NEGV; nI1 = NEGV; ng1 = 0.f;
            }
        }
        int d = u - t;
        bool act = (d >= 0) && (d < 256);
        if (act) {
            float s0[4] = {s0v.x, s0v.y, s0v.z, s0v.w};
            float s1[4] = {s1v.x, s1v.y, s1v.z, s1v.w};
            float go0[4] = {go0v.x, go0v.y, go0v.z, go0v.w};
            float go1[4] = {go1v.x, go1v.y, go1v.z, go1v.w};
            float ge0[4] = {ge0v.x, ge0v.y, ge0v.z, ge0v.w};
            float ge1[4] = {ge1v.x, ge1v.y, ge1v.z, ge1v.w};

            float d0[4], h0[4], iy0[4], g0[4];
            float d1[4], h1[4], iy1[4], g1[4];
            float ixL0 = nI0, dL0 = nD0;       // row 0 left-chain
            float ixL1 = nI1, dL1 = nD1;       // row 1 left-chain
            float ix0_3 = NEGV, ix1_3 = NEGV;  // col-3 ix (boundary)

            #pragma unroll
            for (int c = 0; c < 4; c++) {
                // ---- row 0 (global row 2d) ----
                float diag0 = (c == 0) ? gstale : gS[c - 1];
                float ix0 = lse2b(dL0 - go0[c], ixL0 - ge0[c]);
                iy0[c] = lse2b(hS[c] - go0[c], IyS[c] - ge0[c]);
                d0[c] = s0[c] + diag0;
                h0[c] = lse2b(d0[c], ix0);
                g0[c] = lse3b(h0[c], iy0[c]);
                dL0 = d0[c]; ixL0 = ix0;
                if (c == 3) ix0_3 = ix0;
                // ---- row 1 (global row 2d+1) ----
                float diag1 = (c == 0) ? ng0 : g0[c - 1];
                float ix1 = lse2b(dL1 - go1[c], ixL1 - ge1[c]);
                iy1[c] = lse2b(h0[c] - go1[c], iy0[c] - ge1[c]);
                d1[c] = s1[c] + diag1;
                h1[c] = lse2b(d1[c], ix1);
                g1[c] = lse3b(h1[c], iy1[c]);
                dL1 = d1[c]; ixL1 = ix1;
                if (c == 3) ix1_3 = ix1;
            }

            int oidx = (u * 128 + t) * 2;
            Df4[oidx]     = make_float4(d0[0], d0[1], d0[2], d0[3]);
            Df4[oidx + 1] = make_float4(d1[0], d1[1], d1[2], d1[3]);

            #pragma unroll
            for (int c = 0; c < 4; c++) { hS[c] = h1[c]; IyS[c] = iy1[c]; gS[c] = g1[c]; }
            BD0 = d0[3]; BI0 = ix0_3; Bg0 = g0[3];
            BD1 = d1[3]; BI1 = ix1_3; Bg1 = g1[3];
        }
        gstale = ng1;
        if (lane == 31) {
            sh[par][warp][0] = BD0; sh[par][warp][1] = BI0; sh[par][warp][2] = Bg0;
            sh[par][warp][3] = BD1; sh[par][warp][4] = BI1; sh[par][warp][5] = Bg1;
        }
        __syncthreads();
    };

    for (int i = 0; i < 382; i += 2) {
        step(i, 0);
        step(i + 1, 1);
    }
    step(382, 0);
}

// ================= LSE over valid D slots (base-2 domain) =================
__global__ void lse_part() {
    int blk = blockIdx.x, b = blockIdx.y;    // 48 x 4
    const float4* Dv = g_Df4 + b * (FUU * 256);
    int tid = threadIdx.x;
    float m = NEGV, s = 0.f;
    #pragma unroll
    for (int l = 0; l < 8; l++) {
        int slot = blk * 2048 + tid + l * 256;    // 48*2048 = 98304 = 384*128*2
        int tc = (slot >> 1) & 127, u = slot >> 8;
        int d = u - tc;
        if (d >= 0 && d < 256) {
            float4 v = Dv[slot];
            float m4 = fmaxf(fmaxf(v.x, v.y), fmaxf(v.z, v.w));
            float nm = fmaxf(m, m4);
            s = s * ex2a(m - nm) + ex2a(v.x - nm) + ex2a(v.y - nm)
                                 + ex2a(v.z - nm) + ex2a(v.w - nm);
            m = nm;
        }
    }
    __shared__ float sm[256], ss[256];
    sm[tid] = m; ss[tid] = s;
    __syncthreads();
    for (int o = 128; o > 0; o >>= 1) {
        if (tid < o) {
            float m2 = sm[tid + o], s2 = ss[tid + o];
            float nm = fmaxf(sm[tid], m2);
            ss[tid] = ss[tid] * ex2a(sm[tid] - nm) + s2 * ex2a(m2 - nm);
            sm[tid] = nm;
        }
        __syncthreads();
    }
    if (tid == 0) { g_pm[b * 64 + blk] = sm[0]; g_ps[b * 64 + blk] = ss[0]; }
}

__global__ void lse_final(float* __restrict__ out) {
    int t = threadIdx.x;              // 256
    int b = t >> 6, r = t & 63;
    float m = (r < 48) ? g_pm[b * 64 + r] : NEGV;
    float s = (r < 48) ? g_ps[b * 64 + r] : 0.f;
    __shared__ float sm[256], ss[256], vv[4];
    sm[t] = m; ss[t] = s;
    __syncthreads();
    for (int o = 32; o > 0; o >>= 1) {
        if (r < o) {
            float m2 = sm[t + o], s2 = ss[t + o];
            float nm = fmaxf(sm[t], m2);
            ss[t] = ss[t] * ex2a(sm[t] - nm) + s2 * ex2a(m2 - nm);
            sm[t] = nm;
        }
        __syncthreads();
    }
    if (r == 0) vv[b] = LN2 * (sm[t] + lg2a(ss[t]));
    __syncthreads();
    if (t == 0) out[0] = 0.25f * (vv[0] + vv[1] + vv[2] + vv[3]);
}

// ================= deskew: Df[u][t][r] -> probas (inverse of reskew) ============
__global__ void __launch_bounds__(256) deskew_kernel(float* __restrict__ out) {
    int b = blockIdx.y;
    int dt = blockIdx.x >> 2, tt = blockIdx.x & 3;
    const float4* Df = g_Df4 + b * (FUU * 256);
    int d0 = dt * 32, t0 = tt * 32;
    __shared__ __align__(16) float sm[64][132];
    int tid = threadIdx.x;
    #pragma unroll
    for (int l = 0; l < 8; l++) {
        int e = tid + l * 256;          // 2048 float4
        int r = e & 1, tl = (e >> 1) & 31, dd = e >> 6;
        int u = d0 + dd + t0 + tl;
        *(float4*)&sm[2 * dd + r][4 * tl] = Df[(u * 128 + t0 + tl) * 2 + r];
    }
    __syncthreads();
    float* ob = out + 1 + b * 262144;
    #pragma unroll
    for (int l = 0; l < 32; l++) {
        int e = tid + l * 256;          // 8192 floats
        int rr = e >> 7, cc = e & 127;
        ob[(2 * d0 + rr) * 512 + 4 * t0 + cc] = LN2 * sm[rr][cc];
    }
}

// ================= launcher =================
extern "C" void kernel_launch(void* const* d_in, const int* in_sizes, int n_in,
                              void* d_out, int out_size) {
    const float* x  = (const float*)d_in[0];
    const float* y  = (const float*)d_in[1];
    const float* go = (const float*)d_in[2];
    const float* ge = (const float*)d_in[3];
    float* out = (float*)d_out;

    norm_kernel<<<32, 256>>>(x, y);
    dist_kernel<<<dim3(8, 8, 4), 256>>>(x, y);
    reskew_kernel<<<dim3(32, 6), 256>>>(go, ge);
    sw_kernel<<<4, SWT>>>();
    lse_part<<<dim3(48, 4), 256>>>();
    deskew_kernel<<<dim3(32, 4), 256>>>(out);
    lse_final<<<1, 256>>>(out);
}